// round 15
// baseline (speedup 1.0000x reference)
#include <cuda_runtime.h>
#include <cuda_fp16.h>

#define NMAX 100000
#define EMAX 1600000
#define GMAX 128
#define CHUNK 512

// ---------------- device scratch (zero-init at load; kernels restore zeros) ----------
__device__ uint2  g_hh[2][NMAX * 8];     // h ping-pong buffers, fp16 (64B rows)
__device__ float4 g_y4[NMAX * 8];        // agg output + bias (fp32, consumed by k_nodeT)
__device__ float  g_as[2][NMAX];
__device__ float  g_ad[2][NMAX];
__device__ float  g_vacc[NMAX];          // running readout scalar per node
__device__ int    g_deg[NMAX];           // must be 0 on entry to k_countB
__device__ int    g_rp[NMAX + 1];
__device__ unsigned short g_rank[EMAX];  // edge's rank within its dst bucket
__device__ int    g_perm[NMAX];          // nodes sorted by degree
__device__ int    g_bsum[256];           // per-chunk sums (rewritten)
__device__ int    g_boff[256];           // per-chunk offsets (rewritten)
__device__ int    g_dhist[128];          // degree histogram (must be 0 on entry)
__device__ int    g_dcur[128];           // degree-bucket cursors (rewritten)
__device__ float4 g_pack[EMAX];          // {src_bits, cae0, cae1, cae2} CSR order
__device__ float  g_easum[3];            // must be 0 on entry to k_build (zeroed in k_final)
// g_prm: [0..288) Weff(9x32), [288..320) beff, [320+5l..): u0,u1,u2,c,(unused)
__device__ float  g_prm[352];
__device__ float  g_gsum[GMAX];          // must be 0 on entry to k_agg<2>
__device__ float  g_gcnt[GMAX];

__device__ __forceinline__ float lrelu(float x) { return x > 0.f ? x : 0.2f * x; }
__device__ __forceinline__ float wreduce(float v) {
#pragma unroll
    for (int o = 16; o; o >>= 1) v += __shfl_xor_sync(0xffffffffu, v, o);
    return v;
}
__device__ __forceinline__ int iwreduce(int v) {
#pragma unroll
    for (int o = 16; o; o >>= 1) v += __shfl_xor_sync(0xffffffffu, v, o);
    return v;
}
__device__ __forceinline__ uint2 pack4h(float a, float b, float c, float d) {
    __half2 lo = __floats2half2_rn(a, b);
    __half2 hi = __floats2half2_rn(c, d);
    uint2 r;
    r.x = *(unsigned*)&lo; r.y = *(unsigned*)&hi;
    return r;
}
__device__ __forceinline__ float4 unp4h(uint2 u) {
    float2 a = __half22float2(*(__half2*)&u.x);
    float2 b = __half22float2(*(__half2*)&u.y);
    return make_float4(a.x, a.y, b.x, b.y);
}

// ---------------- 1: degree count, rank recorded (lean: dst only) ----------------
__global__ void __launch_bounds__(256) k_countB(const int* __restrict__ dst, int E) {
    int e = blockIdx.x * 256 + threadIdx.x;
    if (e < E) g_rank[e] = (unsigned short)atomicAdd(&g_deg[dst[e]], 1);
}

// ---------------- 2: chunk sums + degree histogram ----------------
__global__ void __launch_bounds__(256) k_scan1(int n) {
    __shared__ int sw[8];
    __shared__ int hist[128];
    int t = threadIdx.x;
    if (t < 128) hist[t] = 0;
    __syncthreads();
    int base = blockIdx.x * CHUNK + t * 2;
    int s = 0;
#pragma unroll
    for (int k = 0; k < 2; k++) {
        int i = base + k;
        if (i < n) {
            int dv = g_deg[i];
            s += dv;
            atomicAdd(&hist[min(dv, 127)], 1);
        }
    }
    s = iwreduce(s);
    if ((t & 31) == 0) sw[t >> 5] = s;
    __syncthreads();
    if (t < 128 && hist[t]) atomicAdd(&g_dhist[t], hist[t]);
    if (t == 0) {
        int v = 0;
#pragma unroll
        for (int k = 0; k < 8; k++) v += sw[k];
        g_bsum[blockIdx.x] = v;
    }
}

// ---------------- 3: folded params + parallel scans (chunk sums, degree hist) ---------
__global__ void k_scan2(const float* __restrict__ W_ne, const float* __restrict__ b_ne,
                        const float* __restrict__ W_ee, const float* __restrict__ b_ee,
                        const float* __restrict__ W0,
                        const float* __restrict__ We0, const float* __restrict__ ae0,
                        const float* __restrict__ We1, const float* __restrict__ ae1,
                        const float* __restrict__ We2, const float* __restrict__ ae2,
                        int nch, int n, int E) {
    int t = threadIdx.x;
    if (t < 288) {
        int r = t / 32, j = t % 32;
        float s = 0.f;
        for (int d = 0; d < 16; d++) s += W_ne[r * 16 + d] * W0[d * 32 + j];
        g_prm[t] = s;
    } else if (t < 320) {
        int j = t - 288;
        float s = 0.f;
        for (int d = 0; d < 16; d++) s += b_ne[d] * W0[d * 32 + j];
        g_prm[288 + j] = s;
    } else if (t < 416) {
        int l = (t - 320) >> 5, j = t & 31;
        const float* We = (l == 0) ? We0 : (l == 1) ? We1 : We2;
        const float* ae = (l == 0) ? ae0 : (l == 1) ? ae1 : ae2;
        float aej = ae[j];
        float v0 = wreduce(We[j] * aej);
        float v1 = wreduce(We[32 + j] * aej);
        if (j == 0) {
            g_prm[320 + 5 * l + 0] = W_ee[0] * v0 + W_ee[1] * v1;
            g_prm[320 + 5 * l + 1] = W_ee[2] * v0 + W_ee[3] * v1;
            g_prm[320 + 5 * l + 2] = W_ee[4] * v0 + W_ee[5] * v1;
            g_prm[320 + 5 * l + 3] = b_ee[0] * v0 + b_ee[1] * v1;
        }
    } else if (t < 448) {
        // warp 13: exclusive scan of 128-entry degree histogram -> g_dcur
        int lane = t - 416;
        int v[4]; int s = 0;
#pragma unroll
        for (int k = 0; k < 4; k++) { v[k] = g_dhist[lane * 4 + k]; s += v[k]; }
        int sc = s;
#pragma unroll
        for (int o = 1; o < 32; o <<= 1) {
            int u = __shfl_up_sync(0xffffffffu, sc, o);
            if (lane >= o) sc += u;
        }
        int excl = sc - s;
#pragma unroll
        for (int k = 0; k < 4; k++) { g_dcur[lane * 4 + k] = excl; excl += v[k]; }
    } else if (t < 480) {
        // warp 14: exclusive scan of nch (<=256) chunk sums -> g_boff (+ total -> g_rp[n])
        int lane = t - 448;
        int v[8]; int s = 0;
#pragma unroll
        for (int k = 0; k < 8; k++) {
            int idx = lane * 8 + k;
            v[k] = (idx < nch) ? g_bsum[idx] : 0;
            s += v[k];
        }
        int sc = s;
#pragma unroll
        for (int o = 1; o < 32; o <<= 1) {
            int u = __shfl_up_sync(0xffffffffu, sc, o);
            if (lane >= o) sc += u;
        }
        int excl = sc - s;
#pragma unroll
        for (int k = 0; k < 8; k++) {
            int idx = lane * 8 + k;
            if (idx < nch) g_boff[idx] = excl;
            excl += v[k];
        }
        int tot = __shfl_sync(0xffffffffu, sc, 31);
        if (lane == 0) g_rp[n] = tot;
    }
    __syncthreads();
    if (t >= 128 && t < 256) g_dhist[t - 128] = 0;   // restore zeros
}

// ---------------- 4: rp + degree-sort perm (block-aggregated buckets) -------
__global__ void __launch_bounds__(256) k_scan3(int n) {
    __shared__ int swarp[8];
    __shared__ int hist[128];      // block-local bucket counts / rank cursors
    __shared__ int hbase[128];     // block's base offset within each global bucket
    int t = threadIdx.x, lane = t & 31, w = t >> 5;
    if (t < 128) hist[t] = 0;
    __syncthreads();
    int base = blockIdx.x * CHUNK + t * 2;
    int v[2], rk[2]; int s = 0;
#pragma unroll
    for (int k = 0; k < 2; k++) {
        int i = base + k;
        v[k] = (i < n) ? g_deg[i] : 0;
        if (i < n) rk[k] = atomicAdd(&hist[min(v[k], 127)], 1);   // local rank in bucket
        s += v[k];
    }
    int sc = s;
#pragma unroll
    for (int o = 1; o < 32; o <<= 1) {
        int u = __shfl_up_sync(0xffffffffu, sc, o);
        if (lane >= o) sc += u;
    }
    if (lane == 31) swarp[w] = sc;
    __syncthreads();
    if (t == 0) {
        int r = 0;
#pragma unroll
        for (int k = 0; k < 8; k++) { int tmp = swarp[k]; swarp[k] = r; r += tmp; }
    }
    if (t < 128) hbase[t] = hist[t] ? atomicAdd(&g_dcur[t], hist[t]) : 0;
    __syncthreads();
    int excl = sc - s + swarp[w] + g_boff[blockIdx.x];
#pragma unroll
    for (int k = 0; k < 2; k++) {
        int i = base + k;
        if (i < n) {
            g_rp[i] = excl; excl += v[k];
            int b = min(v[k], 127);
            g_perm[hbase[b] + rk[k]] = i;
            g_deg[i] = 0;
        }
    }
}

// ---------------- 5: CSR scatter (rank-based, NO atomics) + easum + layer-0 matmul ----
__global__ void __launch_bounds__(256) k_build(const int* __restrict__ src,
                                               const int* __restrict__ dst,
                                               const float* __restrict__ ea,
                                               const float* __restrict__ nf,
                                               const float* __restrict__ as0,
                                               const float* __restrict__ ad0,
                                               int E, int n, int eb) {
    if ((int)blockIdx.x < eb) {
        __shared__ float sh[3];
        int t = threadIdx.x;
        if (t < 3) sh[t] = 0.f;
        __syncthreads();
        int e = blockIdx.x * 256 + t;
        bool v = e < E;
        float e0 = 0.f, e1 = 0.f, e2 = 0.f;
        int d = 0;
        if (v) {
            d = dst[e];
            e0 = ea[3 * e]; e1 = ea[3 * e + 1]; e2 = ea[3 * e + 2];
        }
        float s0 = wreduce(e0), s1 = wreduce(e1), s2 = wreduce(e2);
        if ((t & 31) == 0) {
            atomicAdd(&sh[0], s0); atomicAdd(&sh[1], s1); atomicAdd(&sh[2], s2);
        }
        if (v) {
            int pos = g_rp[d] + (int)g_rank[e];
            const float* p = &g_prm[320];
            float4 r;
            r.x = __int_as_float(src[e]);
            r.y = e0 * p[0]  + e1 * p[1]  + e2 * p[2]  + p[3];
            r.z = e0 * p[5]  + e1 * p[6]  + e2 * p[7]  + p[8];
            r.w = e0 * p[10] + e1 * p[11] + e2 * p[12] + p[13];
            g_pack[pos] = r;
        }
        __syncthreads();
        if (t < 3) atomicAdd(&g_easum[t], sh[t]);
    } else {
        __shared__ float Ws[288], bs[32], av[64];
        int t = threadIdx.x;
        for (int k = t; k < 288; k += 256) Ws[k] = g_prm[k];
        if (t < 32) { bs[t] = g_prm[288 + t]; av[t] = as0[t]; av[32 + t] = ad0[t]; }
        __syncthreads();
        int i = ((int)blockIdx.x - eb) * 256 + t;
        if (i >= n) return;
        float x[9];
#pragma unroll
        for (int r = 0; r < 9; r++) x[r] = nf[i * 9 + r];
        float acc[32];
#pragma unroll
        for (int j = 0; j < 32; j++) acc[j] = bs[j];
#pragma unroll
        for (int r = 0; r < 9; r++)
#pragma unroll
            for (int j = 0; j < 32; j++) acc[j] += x[r] * Ws[r * 32 + j];
        float sa = 0.f, sd = 0.f;
#pragma unroll
        for (int j = 0; j < 32; j++) { sa += acc[j] * av[j]; sd += acc[j] * av[32 + j]; }
        g_as[0][i] = sa; g_ad[0][i] = sd;
        uint2* o = &g_hh[0][i * 8];
#pragma unroll
        for (int q = 0; q < 8; q++)
            o[q] = pack4h(acc[4 * q], acc[4 * q + 1], acc[4 * q + 2], acc[4 * q + 3]);
    }
}

// ---------------- 6,8,10: agg — 4 nodes/warp, fp16 gather, unrolled 8-trip loop -------
template <int L>
__global__ void __launch_bounds__(256) k_agg(const float* __restrict__ bbc,
                                             const float* __restrict__ Wl3,
                                             const int* __restrict__ batch, int n, float invE) {
    constexpr int P = (L == 1) ? 1 : 0;       // h buffer: L0->0, L1->1, L2->0
    const uint2* hc = g_hh[P];
    int t = threadIdx.x, lane = t & 31, w = t >> 5;
    int node = lane >> 3;      // 0..3
    int hl   = lane & 7;       // lane within node (also column group)
    int slot = (blockIdx.x * 8 + w) * 4 + node;
    bool valid = slot < n;
    int dc = g_perm[valid ? slot : (n - 1)];

    const float* asc = g_as[P];
    float adst_d = g_ad[P][dc];
    float asrc_d = asc[dc];
    const float* pu = &g_prm[320 + 5 * L];
    float aloop = (g_easum[0] * pu[0] + g_easum[1] * pu[1] + g_easum[2] * pu[2]) * invE + pu[3];

    int beg = g_rp[dc], end = g_rp[dc + 1];
    int itersW = __reduce_max_sync(0xffffffffu, (end - beg + 7) >> 3);

    float4 acc = make_float4(0.f, 0.f, 0.f, 0.f);
    float denom = 0.f;
    for (int it = 0; it < itersW; it++) {
        int base = beg + (it << 3);
        int idx = base + hl;
        int s = 0; float ex = 0.f;
        if (idx < end) {
            float4 r = g_pack[idx];
            s = __float_as_int(r.x);
            float ae = (L == 0) ? r.y : (L == 1) ? r.z : r.w;
            ex = __expf(lrelu(asc[s] + adst_d + ae));
        }
        denom += ex;
        // fixed 8-trip unrolled gather: out-of-range lanes carry ex=0; MLP=8
#pragma unroll
        for (int k = 0; k < 8; k++) {
            int sl = (node << 3) + k;
            float exk = __shfl_sync(0xffffffffu, ex, sl);
            int   sk  = __shfl_sync(0xffffffffu, s, sl);
            float4 hv = unp4h(hc[sk * 8 + hl]);
            acc.x += exk * hv.x; acc.y += exk * hv.y;
            acc.z += exk * hv.z; acc.w += exk * hv.w;
        }
    }
    denom += __shfl_xor_sync(0xffffffffu, denom, 1);
    denom += __shfl_xor_sync(0xffffffffu, denom, 2);
    denom += __shfl_xor_sync(0xffffffffu, denom, 4);

    float le = __expf(lrelu(asrc_d + adst_d + aloop));
    float inv = 1.f / (denom + le + 1e-16f);
    float4 hd4 = unp4h(hc[dc * 8 + hl]);
    float4 bb4 = ((const float4*)bbc)[hl];
    float4 wl4 = ((const float4*)Wl3)[L * 8 + hl];
    float4 y4;
    y4.x = (acc.x + le * hd4.x) * inv + bb4.x;
    y4.y = (acc.y + le * hd4.y) * inv + bb4.y;
    y4.z = (acc.z + le * hd4.z) * inv + bb4.z;
    y4.w = (acc.w + le * hd4.w) * inv + bb4.w;
    float v = y4.x * wl4.x + y4.y * wl4.y + y4.z * wl4.z + y4.w * wl4.w;
    v += __shfl_xor_sync(0xffffffffu, v, 1);
    v += __shfl_xor_sync(0xffffffffu, v, 2);
    v += __shfl_xor_sync(0xffffffffu, v, 4);
    if (valid) {
        if (L < 2) {
            g_y4[dc * 8 + hl] = y4;
            if (hl == 0) {
                if (L == 0) g_vacc[dc] = v;
                else        g_vacc[dc] += v;
            }
        } else if (hl == 0) {
            int gg = batch[dc];
            atomicAdd(&g_gsum[gg], g_vacc[dc] + v);
            atomicAdd(&g_gcnt[gg], 1.f);
        }
    }
}

// ---------------- 7,9: node transform h' = y @ W, attn scalars (thread per node) ------
__global__ void __launch_bounds__(256) k_nodeT(const float* __restrict__ W,
                                               const float* __restrict__ as_,
                                               const float* __restrict__ ad_,
                                               int hbuf, int abuf, int n) {
    __shared__ float Ws[1024], av[64];
    int t = threadIdx.x;
    for (int k = t; k < 1024; k += 256) Ws[k] = W[k];
    if (t < 32) { av[t] = as_[t]; av[32 + t] = ad_[t]; }
    __syncthreads();
    int i = blockIdx.x * 256 + t;
    if (i >= n) return;
    const float4* yv4 = &g_y4[i * 8];
    float acc[32];
#pragma unroll
    for (int j = 0; j < 32; j++) acc[j] = 0.f;
#pragma unroll
    for (int q = 0; q < 8; q++) {
        float4 yv = yv4[q];
#pragma unroll
        for (int j = 0; j < 32; j++)
            acc[j] += yv.x * Ws[(4 * q) * 32 + j]     + yv.y * Ws[(4 * q + 1) * 32 + j]
                    + yv.z * Ws[(4 * q + 2) * 32 + j] + yv.w * Ws[(4 * q + 3) * 32 + j];
    }
    float sa = 0.f, sd = 0.f;
#pragma unroll
    for (int j = 0; j < 32; j++) { sa += acc[j] * av[j]; sd += acc[j] * av[32 + j]; }
    g_as[abuf][i] = sa; g_ad[abuf][i] = sd;
    uint2* o = &g_hh[hbuf][i * 8];
#pragma unroll
    for (int q = 0; q < 8; q++)
        o[q] = pack4h(acc[4 * q], acc[4 * q + 1], acc[4 * q + 2], acc[4 * q + 3]);
}

// ---------------- 11: final mean + bias, restore zeros ----------------
__global__ void k_final(float* __restrict__ out, const float* __restrict__ b_l3, int G) {
    int g = blockIdx.x * blockDim.x + threadIdx.x;
    if (g < 3) g_easum[g] = 0.f;
    if (g < G) {
        out[g] = g_gsum[g] / fmaxf(g_gcnt[g], 1.f) + b_l3[0];
        g_gsum[g] = 0.f;
        g_gcnt[g] = 0.f;
    }
}

// ---------------- launch ----------------
extern "C" void kernel_launch(void* const* d_in, const int* in_sizes, int n_in,
                              void* d_out, int out_size) {
    const float* nf    = (const float*)d_in[0];
    const int*   ei    = (const int*)d_in[1];
    const float* ea    = (const float*)d_in[2];
    const int*   batch = (const int*)d_in[3];
    const float* W_ne  = (const float*)d_in[4];
    const float* b_ne  = (const float*)d_in[5];
    const float* W_ee  = (const float*)d_in[6];
    const float* b_ee  = (const float*)d_in[7];
    const float* W_l3  = (const float*)d_in[8];
    const float* b_l3  = (const float*)d_in[9];
    const float* W[3]   = {(const float*)d_in[10], (const float*)d_in[16], (const float*)d_in[22]};
    const float* as_[3] = {(const float*)d_in[11], (const float*)d_in[17], (const float*)d_in[23]};
    const float* ad_[3] = {(const float*)d_in[12], (const float*)d_in[18], (const float*)d_in[24]};
    const float* We_[3] = {(const float*)d_in[13], (const float*)d_in[19], (const float*)d_in[25]};
    const float* ae_[3] = {(const float*)d_in[14], (const float*)d_in[20], (const float*)d_in[26]};
    const float* bb_[3] = {(const float*)d_in[15], (const float*)d_in[21], (const float*)d_in[27]};

    int n = in_sizes[3];
    int E = in_sizes[1] / 2;
    int G = out_size;
    const int* src = ei;
    const int* dst = ei + E;
    float invE = 1.f / (float)E;

    int eb  = (E + 255) / 256;
    int nb  = (n + 255) / 256;
    int nbw = (n + 31) / 32;
    int nch = (n + CHUNK - 1) / CHUNK;

    k_countB<<<eb, 256>>>(dst, E);
    k_scan1<<<nch, 256>>>(n);
    k_scan2<<<1, 512>>>(W_ne, b_ne, W_ee, b_ee, W[0],
                        We_[0], ae_[0], We_[1], ae_[1], We_[2], ae_[2], nch, n, E);
    k_scan3<<<nch, 256>>>(n);
    k_build<<<eb + nb, 256>>>(src, dst, ea, nf, as_[0], ad_[0], E, n, eb);
    k_agg<0><<<nbw, 256>>>(bb_[0], W_l3, batch, n, invE);
    k_nodeT<<<nb, 256>>>(W[1], as_[1], ad_[1], 1, 1, n);
    k_agg<1><<<nbw, 256>>>(bb_[1], W_l3, batch, n, invE);
    k_nodeT<<<nb, 256>>>(W[2], as_[2], ad_[2], 0, 0, n);
    k_agg<2><<<nbw, 256>>>(bb_[2], W_l3, batch, n, invE);
    k_final<<<1, 128>>>((float*)d_out, b_l3, G);
}

// round 16
// speedup vs baseline: 1.0373x; 1.0373x over previous
#include <cuda_runtime.h>
#include <cuda_fp16.h>

#define NMAX 100000
#define EMAX 1600000
#define GMAX 128
#define CHUNK 512

// ---------------- device scratch (zero-init at load; kernels restore zeros) ----------
__device__ uint2  g_hh[2][NMAX * 8];     // h ping-pong buffers, fp16 (64B rows)
__device__ float4 g_y4[NMAX * 8];        // agg output + bias (fp32, consumed by k_nodeT)
__device__ float  g_as[2][NMAX];
__device__ float  g_ad[2][NMAX];
__device__ float  g_vacc[NMAX];          // running readout scalar per node
__device__ int    g_deg[NMAX];           // must be 0 on entry to k_countB
__device__ int    g_rp[NMAX + 1];
__device__ int    g_cur[NMAX];           // scatter cursors (rewritten each launch)
__device__ int    g_perm[NMAX];          // nodes sorted by degree
__device__ int    g_bsum[256];           // per-chunk sums (rewritten)
__device__ int    g_boff[256];           // per-chunk offsets (rewritten)
__device__ int    g_dhist[128];          // degree histogram (must be 0 on entry)
__device__ int    g_dcur[128];           // degree-bucket cursors (rewritten)
__device__ float4 g_pack[EMAX];          // {src_bits, cae0, cae1, cae2} CSR order
__device__ float  g_easum[3];            // must be 0 on entry to k_countB
// g_prm: [0..288) Weff(9x32), [288..320) beff, [320+5l..): u0,u1,u2,c,aloop
__device__ float  g_prm[352];
__device__ float  g_gsum[GMAX];          // must be 0 on entry to k_agg<2>
__device__ float  g_gcnt[GMAX];

__device__ __forceinline__ float lrelu(float x) { return x > 0.f ? x : 0.2f * x; }
__device__ __forceinline__ float wreduce(float v) {
#pragma unroll
    for (int o = 16; o; o >>= 1) v += __shfl_xor_sync(0xffffffffu, v, o);
    return v;
}
__device__ __forceinline__ int iwreduce(int v) {
#pragma unroll
    for (int o = 16; o; o >>= 1) v += __shfl_xor_sync(0xffffffffu, v, o);
    return v;
}
__device__ __forceinline__ uint2 pack4h(float a, float b, float c, float d) {
    __half2 lo = __floats2half2_rn(a, b);
    __half2 hi = __floats2half2_rn(c, d);
    uint2 r;
    r.x = *(unsigned*)&lo; r.y = *(unsigned*)&hi;
    return r;
}
__device__ __forceinline__ float4 unp4h(uint2 u) {
    float2 a = __half22float2(*(__half2*)&u.x);
    float2 b = __half22float2(*(__half2*)&u.y);
    return make_float4(a.x, a.y, b.x, b.y);
}

// ---------------- 1: degree count (RED, no return) + edge_attr column sums ------------
__global__ void k_countB(const int* __restrict__ dst, const float* __restrict__ ea, int E) {
    __shared__ float sh[3];
    if (threadIdx.x < 3) sh[threadIdx.x] = 0.f;
    __syncthreads();
    float s0 = 0.f, s1 = 0.f, s2 = 0.f;
    for (int e = blockIdx.x * blockDim.x + threadIdx.x; e < E; e += gridDim.x * blockDim.x) {
        atomicAdd(&g_deg[dst[e]], 1);
        s0 += ea[3 * e]; s1 += ea[3 * e + 1]; s2 += ea[3 * e + 2];
    }
    s0 = wreduce(s0); s1 = wreduce(s1); s2 = wreduce(s2);
    if ((threadIdx.x & 31) == 0) {
        atomicAdd(&sh[0], s0); atomicAdd(&sh[1], s1); atomicAdd(&sh[2], s2);
    }
    __syncthreads();
    if (threadIdx.x < 3) atomicAdd(&g_easum[threadIdx.x], sh[threadIdx.x]);
}

// ---------------- 2: chunk sums + degree histogram ----------------
__global__ void __launch_bounds__(256) k_scan1(int n) {
    __shared__ int sw[8];
    __shared__ int hist[128];
    int t = threadIdx.x;
    if (t < 128) hist[t] = 0;
    __syncthreads();
    int base = blockIdx.x * CHUNK + t * 2;
    int s = 0;
#pragma unroll
    for (int k = 0; k < 2; k++) {
        int i = base + k;
        if (i < n) {
            int dv = g_deg[i];
            s += dv;
            atomicAdd(&hist[min(dv, 127)], 1);
        }
    }
    s = iwreduce(s);
    if ((t & 31) == 0) sw[t >> 5] = s;
    __syncthreads();
    if (t < 128 && hist[t]) atomicAdd(&g_dhist[t], hist[t]);
    if (t == 0) {
        int v = 0;
#pragma unroll
        for (int k = 0; k < 8; k++) v += sw[k];
        g_bsum[blockIdx.x] = v;
    }
}

// ---------------- 3: folded params + parallel scans (chunk sums, degree hist) ---------
__global__ void k_scan2(const float* __restrict__ W_ne, const float* __restrict__ b_ne,
                        const float* __restrict__ W_ee, const float* __restrict__ b_ee,
                        const float* __restrict__ W0,
                        const float* __restrict__ We0, const float* __restrict__ ae0,
                        const float* __restrict__ We1, const float* __restrict__ ae1,
                        const float* __restrict__ We2, const float* __restrict__ ae2,
                        int nch, int n, int E) {
    int t = threadIdx.x;
    if (t < 288) {
        int r = t / 32, j = t % 32;
        float s = 0.f;
        for (int d = 0; d < 16; d++) s += W_ne[r * 16 + d] * W0[d * 32 + j];
        g_prm[t] = s;
    } else if (t < 320) {
        int j = t - 288;
        float s = 0.f;
        for (int d = 0; d < 16; d++) s += b_ne[d] * W0[d * 32 + j];
        g_prm[288 + j] = s;
    } else if (t < 416) {
        int l = (t - 320) >> 5, j = t & 31;
        const float* We = (l == 0) ? We0 : (l == 1) ? We1 : We2;
        const float* ae = (l == 0) ? ae0 : (l == 1) ? ae1 : ae2;
        float aej = ae[j];
        float v0 = wreduce(We[j] * aej);
        float v1 = wreduce(We[32 + j] * aej);
        if (j == 0) {
            float u0 = W_ee[0] * v0 + W_ee[1] * v1;
            float u1 = W_ee[2] * v0 + W_ee[3] * v1;
            float u2 = W_ee[4] * v0 + W_ee[5] * v1;
            float c  = b_ee[0] * v0 + b_ee[1] * v1;
            float inv = 1.f / (float)E;
            g_prm[320 + 5 * l + 0] = u0;
            g_prm[320 + 5 * l + 1] = u1;
            g_prm[320 + 5 * l + 2] = u2;
            g_prm[320 + 5 * l + 3] = c;
            g_prm[320 + 5 * l + 4] = g_easum[0] * inv * u0 + g_easum[1] * inv * u1
                                   + g_easum[2] * inv * u2 + c;
        }
    } else if (t < 448) {
        // warp 13: exclusive scan of 128-entry degree histogram -> g_dcur
        int lane = t - 416;
        int v[4]; int s = 0;
#pragma unroll
        for (int k = 0; k < 4; k++) { v[k] = g_dhist[lane * 4 + k]; s += v[k]; }
        int sc = s;
#pragma unroll
        for (int o = 1; o < 32; o <<= 1) {
            int u = __shfl_up_sync(0xffffffffu, sc, o);
            if (lane >= o) sc += u;
        }
        int excl = sc - s;
#pragma unroll
        for (int k = 0; k < 4; k++) { g_dcur[lane * 4 + k] = excl; excl += v[k]; }
    } else if (t < 480) {
        // warp 14: exclusive scan of nch (<=256) chunk sums -> g_boff (+ total -> g_rp[n])
        int lane = t - 448;
        int v[8]; int s = 0;
#pragma unroll
        for (int k = 0; k < 8; k++) {
            int idx = lane * 8 + k;
            v[k] = (idx < nch) ? g_bsum[idx] : 0;
            s += v[k];
        }
        int sc = s;
#pragma unroll
        for (int o = 1; o < 32; o <<= 1) {
            int u = __shfl_up_sync(0xffffffffu, sc, o);
            if (lane >= o) sc += u;
        }
        int excl = sc - s;
#pragma unroll
        for (int k = 0; k < 8; k++) {
            int idx = lane * 8 + k;
            if (idx < nch) g_boff[idx] = excl;
            excl += v[k];
        }
        int tot = __shfl_sync(0xffffffffu, sc, 31);
        if (lane == 0) g_rp[n] = tot;
    }
    __syncthreads();
    if (t < 3) g_easum[t] = 0.f;                   // restore zeros
    if (t >= 128 && t < 256) g_dhist[t - 128] = 0;
}

// ---------------- 4: rp + cursors + degree-sort perm (block-aggregated buckets) -------
__global__ void __launch_bounds__(256) k_scan3(int n) {
    __shared__ int swarp[8];
    __shared__ int hist[128];      // block-local bucket counts / rank cursors
    __shared__ int hbase[128];     // block's base offset within each global bucket
    int t = threadIdx.x, lane = t & 31, w = t >> 5;
    if (t < 128) hist[t] = 0;
    __syncthreads();
    int base = blockIdx.x * CHUNK + t * 2;
    int v[2], rk[2]; int s = 0;
#pragma unroll
    for (int k = 0; k < 2; k++) {
        int i = base + k;
        v[k] = (i < n) ? g_deg[i] : 0;
        if (i < n) rk[k] = atomicAdd(&hist[min(v[k], 127)], 1);   // local rank in bucket
        s += v[k];
    }
    int sc = s;
#pragma unroll
    for (int o = 1; o < 32; o <<= 1) {
        int u = __shfl_up_sync(0xffffffffu, sc, o);
        if (lane >= o) sc += u;
    }
    if (lane == 31) swarp[w] = sc;
    __syncthreads();
    if (t == 0) {
        int r = 0;
#pragma unroll
        for (int k = 0; k < 8; k++) { int tmp = swarp[k]; swarp[k] = r; r += tmp; }
    }
    // one global atomic per non-empty bucket per block
    if (t < 128) hbase[t] = hist[t] ? atomicAdd(&g_dcur[t], hist[t]) : 0;
    __syncthreads();
    int excl = sc - s + swarp[w] + g_boff[blockIdx.x];
#pragma unroll
    for (int k = 0; k < 2; k++) {
        int i = base + k;
        if (i < n) {
            g_rp[i] = excl; g_cur[i] = excl; excl += v[k];
            int b = min(v[k], 127);
            g_perm[hbase[b] + rk[k]] = i;
            g_deg[i] = 0;
        }
    }
}

// ---------------- 5: CSR scatter (atomic cursors) + layer-0 node matmul ---------------
__global__ void __launch_bounds__(256) k_build(const int* __restrict__ src,
                                               const int* __restrict__ dst,
                                               const float* __restrict__ ea,
                                               const float* __restrict__ nf,
                                               const float* __restrict__ as0,
                                               const float* __restrict__ ad0,
                                               int E, int n, int eb) {
    if ((int)blockIdx.x < eb) {
        int e = blockIdx.x * 256 + threadIdx.x;
        if (e >= E) return;
        int d = dst[e];
        int pos = atomicAdd(&g_cur[d], 1);
        float e0 = ea[3 * e], e1 = ea[3 * e + 1], e2 = ea[3 * e + 2];
        const float* p = &g_prm[320];
        float4 r;
        r.x = __int_as_float(src[e]);
        r.y = e0 * p[0]  + e1 * p[1]  + e2 * p[2]  + p[3];
        r.z = e0 * p[5]  + e1 * p[6]  + e2 * p[7]  + p[8];
        r.w = e0 * p[10] + e1 * p[11] + e2 * p[12] + p[13];
        g_pack[pos] = r;
    } else {
        __shared__ float Ws[288], bs[32], av[64];
        int t = threadIdx.x;
        for (int k = t; k < 288; k += 256) Ws[k] = g_prm[k];
        if (t < 32) { bs[t] = g_prm[288 + t]; av[t] = as0[t]; av[32 + t] = ad0[t]; }
        __syncthreads();
        int i = ((int)blockIdx.x - eb) * 256 + t;
        if (i >= n) return;
        float x[9];
#pragma unroll
        for (int r = 0; r < 9; r++) x[r] = nf[i * 9 + r];
        float acc[32];
#pragma unroll
        for (int j = 0; j < 32; j++) acc[j] = bs[j];
#pragma unroll
        for (int r = 0; r < 9; r++)
#pragma unroll
            for (int j = 0; j < 32; j++) acc[j] += x[r] * Ws[r * 32 + j];
        float sa = 0.f, sd = 0.f;
#pragma unroll
        for (int j = 0; j < 32; j++) { sa += acc[j] * av[j]; sd += acc[j] * av[32 + j]; }
        g_as[0][i] = sa; g_ad[0][i] = sd;
        uint2* o = &g_hh[0][i * 8];
#pragma unroll
        for (int q = 0; q < 8; q++)
            o[q] = pack4h(acc[4 * q], acc[4 * q + 1], acc[4 * q + 2], acc[4 * q + 3]);
    }
}

// ---------------- 6,8,10: agg — 4 nodes/warp, fp16 gather, unrolled 8-trip loop -------
template <int L>
__global__ void __launch_bounds__(256) k_agg(const float* __restrict__ bbc,
                                             const float* __restrict__ Wl3,
                                             const int* __restrict__ batch, int n) {
    constexpr int P = (L == 1) ? 1 : 0;       // h buffer: L0->0, L1->1, L2->0
    const uint2* hc = g_hh[P];
    int t = threadIdx.x, lane = t & 31, w = t >> 5;
    int node = lane >> 3;      // 0..3
    int hl   = lane & 7;       // lane within node (also column group)
    int slot = (blockIdx.x * 8 + w) * 4 + node;
    bool valid = slot < n;
    int dc = g_perm[valid ? slot : (n - 1)];

    const float* asc = g_as[P];
    float adst_d = g_ad[P][dc];
    float asrc_d = asc[dc];
    float aloop = g_prm[320 + 5 * L + 4];

    int beg = g_rp[dc], end = g_rp[dc + 1];
    int itersW = __reduce_max_sync(0xffffffffu, (end - beg + 7) >> 3);

    float4 acc = make_float4(0.f, 0.f, 0.f, 0.f);
    float denom = 0.f;
    for (int it = 0; it < itersW; it++) {
        int base = beg + (it << 3);
        int idx = base + hl;
        int s = 0; float ex = 0.f;
        if (idx < end) {
            float4 r = g_pack[idx];
            s = __float_as_int(r.x);
            float ae = (L == 0) ? r.y : (L == 1) ? r.z : r.w;
            ex = __expf(lrelu(asc[s] + adst_d + ae));
        }
        denom += ex;
        // fixed 8-trip unrolled gather: out-of-range lanes carry ex=0; MLP=8
#pragma unroll
        for (int k = 0; k < 8; k++) {
            int sl = (node << 3) + k;
            float exk = __shfl_sync(0xffffffffu, ex, sl);
            int   sk  = __shfl_sync(0xffffffffu, s, sl);
            float4 hv = unp4h(hc[sk * 8 + hl]);
            acc.x += exk * hv.x; acc.y += exk * hv.y;
            acc.z += exk * hv.z; acc.w += exk * hv.w;
        }
    }
    denom += __shfl_xor_sync(0xffffffffu, denom, 1);
    denom += __shfl_xor_sync(0xffffffffu, denom, 2);
    denom += __shfl_xor_sync(0xffffffffu, denom, 4);

    float le = __expf(lrelu(asrc_d + adst_d + aloop));
    float inv = 1.f / (denom + le + 1e-16f);
    float4 hd4 = unp4h(hc[dc * 8 + hl]);
    float4 bb4 = ((const float4*)bbc)[hl];
    float4 wl4 = ((const float4*)Wl3)[L * 8 + hl];
    float4 y4;
    y4.x = (acc.x + le * hd4.x) * inv + bb4.x;
    y4.y = (acc.y + le * hd4.y) * inv + bb4.y;
    y4.z = (acc.z + le * hd4.z) * inv + bb4.z;
    y4.w = (acc.w + le * hd4.w) * inv + bb4.w;
    float v = y4.x * wl4.x + y4.y * wl4.y + y4.z * wl4.z + y4.w * wl4.w;
    v += __shfl_xor_sync(0xffffffffu, v, 1);
    v += __shfl_xor_sync(0xffffffffu, v, 2);
    v += __shfl_xor_sync(0xffffffffu, v, 4);
    if (valid) {
        if (L < 2) {
            g_y4[dc * 8 + hl] = y4;
            if (hl == 0) {
                if (L == 0) g_vacc[dc] = v;
                else        g_vacc[dc] += v;
            }
        } else if (hl == 0) {
            int gg = batch[dc];
            atomicAdd(&g_gsum[gg], g_vacc[dc] + v);
            atomicAdd(&g_gcnt[gg], 1.f);
        }
    }
}

// ---------------- 7,9: node transform h' = y @ W, attn scalars (thread per node) ------
__global__ void __launch_bounds__(256) k_nodeT(const float* __restrict__ W,
                                               const float* __restrict__ as_,
                                               const float* __restrict__ ad_,
                                               int hbuf, int abuf, int n) {
    __shared__ float Ws[1024], av[64];
    int t = threadIdx.x;
    for (int k = t; k < 1024; k += 256) Ws[k] = W[k];
    if (t < 32) { av[t] = as_[t]; av[32 + t] = ad_[t]; }
    __syncthreads();
    int i = blockIdx.x * 256 + t;
    if (i >= n) return;
    const float4* yv4 = &g_y4[i * 8];
    float acc[32];
#pragma unroll
    for (int j = 0; j < 32; j++) acc[j] = 0.f;
#pragma unroll
    for (int q = 0; q < 8; q++) {
        float4 yv = yv4[q];
#pragma unroll
        for (int j = 0; j < 32; j++)
            acc[j] += yv.x * Ws[(4 * q) * 32 + j]     + yv.y * Ws[(4 * q + 1) * 32 + j]
                    + yv.z * Ws[(4 * q + 2) * 32 + j] + yv.w * Ws[(4 * q + 3) * 32 + j];
    }
    float sa = 0.f, sd = 0.f;
#pragma unroll
    for (int j = 0; j < 32; j++) { sa += acc[j] * av[j]; sd += acc[j] * av[32 + j]; }
    g_as[abuf][i] = sa; g_ad[abuf][i] = sd;
    uint2* o = &g_hh[hbuf][i * 8];
#pragma unroll
    for (int q = 0; q < 8; q++)
        o[q] = pack4h(acc[4 * q], acc[4 * q + 1], acc[4 * q + 2], acc[4 * q + 3]);
}

// ---------------- 11: final mean + bias, restore zeros ----------------
__global__ void k_final(float* __restrict__ out, const float* __restrict__ b_l3, int G) {
    int g = blockIdx.x * blockDim.x + threadIdx.x;
    if (g < G) {
        out[g] = g_gsum[g] / fmaxf(g_gcnt[g], 1.f) + b_l3[0];
        g_gsum[g] = 0.f;
        g_gcnt[g] = 0.f;
    }
}

// ---------------- launch ----------------
extern "C" void kernel_launch(void* const* d_in, const int* in_sizes, int n_in,
                              void* d_out, int out_size) {
    const float* nf    = (const float*)d_in[0];
    const int*   ei    = (const int*)d_in[1];
    const float* ea    = (const float*)d_in[2];
    const int*   batch = (const int*)d_in[3];
    const float* W_ne  = (const float*)d_in[4];
    const float* b_ne  = (const float*)d_in[5];
    const float* W_ee  = (const float*)d_in[6];
    const float* b_ee  = (const float*)d_in[7];
    const float* W_l3  = (const float*)d_in[8];
    const float* b_l3  = (const float*)d_in[9];
    const float* W[3]   = {(const float*)d_in[10], (const float*)d_in[16], (const float*)d_in[22]};
    const float* as_[3] = {(const float*)d_in[11], (const float*)d_in[17], (const float*)d_in[23]};
    const float* ad_[3] = {(const float*)d_in[12], (const float*)d_in[18], (const float*)d_in[24]};
    const float* We_[3] = {(const float*)d_in[13], (const float*)d_in[19], (const float*)d_in[25]};
    const float* ae_[3] = {(const float*)d_in[14], (const float*)d_in[20], (const float*)d_in[26]};
    const float* bb_[3] = {(const float*)d_in[15], (const float*)d_in[21], (const float*)d_in[27]};

    int n = in_sizes[3];
    int E = in_sizes[1] / 2;
    int G = out_size;
    const int* src = ei;
    const int* dst = ei + E;

    int eb  = (E + 255) / 256;
    int nb  = (n + 255) / 256;
    int nbw = (n + 31) / 32;
    int nch = (n + CHUNK - 1) / CHUNK;

    k_countB<<<1184, 256>>>(dst, ea, E);
    k_scan1<<<nch, 256>>>(n);
    k_scan2<<<1, 512>>>(W_ne, b_ne, W_ee, b_ee, W[0],
                        We_[0], ae_[0], We_[1], ae_[1], We_[2], ae_[2], nch, n, E);
    k_scan3<<<nch, 256>>>(n);
    k_build<<<eb + nb, 256>>>(src, dst, ea, nf, as_[0], ad_[0], E, n, eb);
    k_agg<0><<<nbw, 256>>>(bb_[0], W_l3, batch, n);
    k_nodeT<<<nb, 256>>>(W[1], as_[1], ad_[1], 1, 1, n);
    k_agg<1><<<nbw, 256>>>(bb_[1], W_l3, batch, n);
    k_nodeT<<<nb, 256>>>(W[2], as_[2], ad_[2], 0, 0, n);
    k_agg<2><<<nbw, 256>>>(bb_[2], W_l3, batch, n);
    k_final<<<1, 128>>>((float*)d_out, b_l3, G);
}

// round 17
// speedup vs baseline: 1.1646x; 1.1228x over previous
#include <cuda_runtime.h>
#include <cuda_fp16.h>

#define NMAX 100000
#define EMAX 1600000
#define GMAX 128
#define CHUNK 512

// ---------------- device scratch (zero-init at load; kernels restore zeros) ----------
__device__ uint2  g_hh[2][NMAX * 8];     // h ping-pong buffers, fp16 (64B rows)
__device__ float4 g_y4[NMAX * 8];        // agg output + bias (fp32, consumed by k_nodeT)
__device__ float  g_as[2][NMAX];
__device__ float  g_ad[2][NMAX];
__device__ float  g_vacc[NMAX];          // running readout scalar per node
__device__ int    g_deg[NMAX];           // must be 0 on entry to k_countB
__device__ int    g_rp[NMAX + 1];
__device__ int    g_cur[NMAX];           // scatter cursors (rewritten each launch)
__device__ int    g_perm[NMAX];          // nodes sorted by degree
__device__ int    g_bsum[256];           // per-chunk sums (rewritten)
__device__ int    g_boff[256];           // per-chunk offsets (rewritten)
__device__ int    g_dhist[128];          // degree histogram (must be 0 on entry)
__device__ int    g_dcur[128];           // degree-bucket cursors (rewritten)
__device__ float4 g_pack[EMAX];          // {src_bits, cae0, cae1, cae2} CSR order
__device__ float  g_easum[3];            // must be 0 on entry to k_build (zeroed in k_final)
__device__ volatile int g_bc0;           // grid barrier counters (zeroed in k_final)
__device__ volatile int g_bc1;
// g_prm: [0..288) Weff(9x32), [288..320) beff, [320+5l..): u0,u1,u2,c
__device__ float  g_prm[352];
__device__ float  g_gsum[GMAX];          // must be 0 on entry to k_agg<2>
__device__ float  g_gcnt[GMAX];

__device__ __forceinline__ float lrelu(float x) { return x > 0.f ? x : 0.2f * x; }
__device__ __forceinline__ float wreduce(float v) {
#pragma unroll
    for (int o = 16; o; o >>= 1) v += __shfl_xor_sync(0xffffffffu, v, o);
    return v;
}
__device__ __forceinline__ int iwreduce(int v) {
#pragma unroll
    for (int o = 16; o; o >>= 1) v += __shfl_xor_sync(0xffffffffu, v, o);
    return v;
}
__device__ __forceinline__ uint2 pack4h(float a, float b, float c, float d) {
    __half2 lo = __floats2half2_rn(a, b);
    __half2 hi = __floats2half2_rn(c, d);
    uint2 r;
    r.x = *(unsigned*)&lo; r.y = *(unsigned*)&hi;
    return r;
}
__device__ __forceinline__ float4 unp4h(uint2 u) {
    float2 a = __half22float2(*(__half2*)&u.x);
    float2 b = __half22float2(*(__half2*)&u.y);
    return make_float4(a.x, a.y, b.x, b.y);
}
__device__ __forceinline__ void gbar(volatile int* c, int goal) {
    __syncthreads();
    if (threadIdx.x == 0) {
        __threadfence();
        atomicAdd((int*)c, 1);
        while (*c < goal) { }
        __threadfence();
    }
    __syncthreads();
}

// ---------------- 1: degree count (RED, no return; lean) ----------------
__global__ void __launch_bounds__(256) k_countB(const int* __restrict__ dst, int E) {
    int e = blockIdx.x * 256 + threadIdx.x;
    if (e < E) atomicAdd(&g_deg[dst[e]], 1);
}

// ---------------- 2: fused scans (chunk sums+hist | params+meta scans | rp+perm) ------
__global__ void __launch_bounds__(256) k_scans(const float* __restrict__ W_ne,
                                               const float* __restrict__ b_ne,
                                               const float* __restrict__ W_ee,
                                               const float* __restrict__ b_ee,
                                               const float* __restrict__ W0,
                                               const float* __restrict__ We0, const float* __restrict__ ae0,
                                               const float* __restrict__ We1, const float* __restrict__ ae1,
                                               const float* __restrict__ We2, const float* __restrict__ ae2,
                                               int nch, int n) {
    int t = threadIdx.x;
    int nblocks = nch + 1;
    bool isMeta = ((int)blockIdx.x == nch);

    __shared__ int sw[8];
    __shared__ int hist[128];
    __shared__ int hbase[128];

    // ---- phase 1 ----
    if (!isMeta) {
        if (t < 128) hist[t] = 0;
        __syncthreads();
        int base = blockIdx.x * CHUNK + t * 2;
        int s = 0;
#pragma unroll
        for (int k = 0; k < 2; k++) {
            int i = base + k;
            if (i < n) {
                int dv = g_deg[i];
                s += dv;
                atomicAdd(&hist[min(dv, 127)], 1);
            }
        }
        s = iwreduce(s);
        if ((t & 31) == 0) sw[t >> 5] = s;
        __syncthreads();
        if (t < 128 && hist[t]) atomicAdd(&g_dhist[t], hist[t]);
        if (t == 0) {
            int v = 0;
#pragma unroll
            for (int k = 0; k < 8; k++) v += sw[k];
            g_bsum[blockIdx.x] = v;
        }
    } else {
        // meta block: folded params (independent of scans)
        for (int k = t; k < 288; k += 256) {
            int r = k / 32, j = k % 32;
            float s = 0.f;
            for (int d = 0; d < 16; d++) s += W_ne[r * 16 + d] * W0[d * 32 + j];
            g_prm[k] = s;
        }
        if (t < 32) {
            float s = 0.f;
            for (int d = 0; d < 16; d++) s += b_ne[d] * W0[d * 32 + t];
            g_prm[288 + t] = s;
        }
        if (t >= 64 && t < 160) {
            int l = (t - 64) >> 5, j = t & 31;
            const float* We = (l == 0) ? We0 : (l == 1) ? We1 : We2;
            const float* ae = (l == 0) ? ae0 : (l == 1) ? ae1 : ae2;
            float aej = ae[j];
            float v0 = wreduce(We[j] * aej);
            float v1 = wreduce(We[32 + j] * aej);
            if (j == 0) {
                g_prm[320 + 5 * l + 0] = W_ee[0] * v0 + W_ee[1] * v1;
                g_prm[320 + 5 * l + 1] = W_ee[2] * v0 + W_ee[3] * v1;
                g_prm[320 + 5 * l + 2] = W_ee[4] * v0 + W_ee[5] * v1;
                g_prm[320 + 5 * l + 3] = b_ee[0] * v0 + b_ee[1] * v1;
            }
        }
    }

    gbar(&g_bc0, nblocks);

    // ---- phase 2 (meta block only): scan dhist -> dcur, scan bsum -> boff ----
    if (isMeta) {
        if (t < 32) {
            int lane = t;
            int v[4]; int s = 0;
#pragma unroll
            for (int k = 0; k < 4; k++) { v[k] = g_dhist[lane * 4 + k]; s += v[k]; }
            int sc = s;
#pragma unroll
            for (int o = 1; o < 32; o <<= 1) {
                int u = __shfl_up_sync(0xffffffffu, sc, o);
                if (lane >= o) sc += u;
            }
            int excl = sc - s;
#pragma unroll
            for (int k = 0; k < 4; k++) { g_dcur[lane * 4 + k] = excl; excl += v[k]; }
        } else if (t >= 32 && t < 64) {
            int lane = t - 32;
            int v[8]; int s = 0;
#pragma unroll
            for (int k = 0; k < 8; k++) {
                int idx = lane * 8 + k;
                v[k] = (idx < nch) ? g_bsum[idx] : 0;
                s += v[k];
            }
            int sc = s;
#pragma unroll
            for (int o = 1; o < 32; o <<= 1) {
                int u = __shfl_up_sync(0xffffffffu, sc, o);
                if (lane >= o) sc += u;
            }
            int excl = sc - s;
#pragma unroll
            for (int k = 0; k < 8; k++) {
                int idx = lane * 8 + k;
                if (idx < nch) g_boff[idx] = excl;
                excl += v[k];
            }
            int tot = __shfl_sync(0xffffffffu, sc, 31);
            if (lane == 0) g_rp[n] = tot;
        }
    }

    gbar(&g_bc1, nblocks);

    // ---- phase 3: rp + cursors + degree-sort perm; meta block resets dhist ----
    if (isMeta) {
        if (t < 128) g_dhist[t] = 0;
        return;
    }
    if (t < 128) hist[t] = 0;
    __syncthreads();
    int base = blockIdx.x * CHUNK + t * 2;
    int v[2], rk[2]; int s = 0;
#pragma unroll
    for (int k = 0; k < 2; k++) {
        int i = base + k;
        v[k] = (i < n) ? g_deg[i] : 0;
        if (i < n) rk[k] = atomicAdd(&hist[min(v[k], 127)], 1);
        s += v[k];
    }
    int lane = t & 31, w = t >> 5;
    int sc = s;
#pragma unroll
    for (int o = 1; o < 32; o <<= 1) {
        int u = __shfl_up_sync(0xffffffffu, sc, o);
        if (lane >= o) sc += u;
    }
    if (lane == 31) sw[w] = sc;
    __syncthreads();
    if (t == 0) {
        int r = 0;
#pragma unroll
        for (int k = 0; k < 8; k++) { int tmp = sw[k]; sw[k] = r; r += tmp; }
    }
    if (t < 128) hbase[t] = hist[t] ? atomicAdd(&g_dcur[t], hist[t]) : 0;
    __syncthreads();
    int excl = sc - s + sw[w] + g_boff[blockIdx.x];
#pragma unroll
    for (int k = 0; k < 2; k++) {
        int i = base + k;
        if (i < n) {
            g_rp[i] = excl; g_cur[i] = excl; excl += v[k];
            int b = min(v[k], 127);
            g_perm[hbase[b] + rk[k]] = i;
            g_deg[i] = 0;
        }
    }
}

// ---------------- 3: CSR scatter (atomic cursors) + easum + layer-0 node matmul -------
__global__ void __launch_bounds__(256) k_build(const int* __restrict__ src,
                                               const int* __restrict__ dst,
                                               const float* __restrict__ ea,
                                               const float* __restrict__ nf,
                                               const float* __restrict__ as0,
                                               const float* __restrict__ ad0,
                                               int E, int n, int eb) {
    if ((int)blockIdx.x < eb) {
        __shared__ float sh[3];
        int t = threadIdx.x;
        if (t < 3) sh[t] = 0.f;
        __syncthreads();
        int e = blockIdx.x * 256 + t;
        bool v = e < E;
        float e0 = 0.f, e1 = 0.f, e2 = 0.f;
        int d = 0;
        if (v) {
            d = dst[e];
            e0 = ea[3 * e]; e1 = ea[3 * e + 1]; e2 = ea[3 * e + 2];
        }
        float s0 = wreduce(e0), s1 = wreduce(e1), s2 = wreduce(e2);
        if ((t & 31) == 0) {
            atomicAdd(&sh[0], s0); atomicAdd(&sh[1], s1); atomicAdd(&sh[2], s2);
        }
        if (v) {
            int pos = atomicAdd(&g_cur[d], 1);
            const float* p = &g_prm[320];
            float4 r;
            r.x = __int_as_float(src[e]);
            r.y = e0 * p[0]  + e1 * p[1]  + e2 * p[2]  + p[3];
            r.z = e0 * p[5]  + e1 * p[6]  + e2 * p[7]  + p[8];
            r.w = e0 * p[10] + e1 * p[11] + e2 * p[12] + p[13];
            g_pack[pos] = r;
        }
        __syncthreads();
        if (t < 3) atomicAdd(&g_easum[t], sh[t]);
    } else {
        __shared__ float Ws[288], bs[32], av[64];
        int t = threadIdx.x;
        for (int k = t; k < 288; k += 256) Ws[k] = g_prm[k];
        if (t < 32) { bs[t] = g_prm[288 + t]; av[t] = as0[t]; av[32 + t] = ad0[t]; }
        __syncthreads();
        int i = ((int)blockIdx.x - eb) * 256 + t;
        if (i >= n) return;
        float x[9];
#pragma unroll
        for (int r = 0; r < 9; r++) x[r] = nf[i * 9 + r];
        float acc[32];
#pragma unroll
        for (int j = 0; j < 32; j++) acc[j] = bs[j];
#pragma unroll
        for (int r = 0; r < 9; r++)
#pragma unroll
            for (int j = 0; j < 32; j++) acc[j] += x[r] * Ws[r * 32 + j];
        float sa = 0.f, sd = 0.f;
#pragma unroll
        for (int j = 0; j < 32; j++) { sa += acc[j] * av[j]; sd += acc[j] * av[32 + j]; }
        g_as[0][i] = sa; g_ad[0][i] = sd;
        uint2* o = &g_hh[0][i * 8];
#pragma unroll
        for (int q = 0; q < 8; q++)
            o[q] = pack4h(acc[4 * q], acc[4 * q + 1], acc[4 * q + 2], acc[4 * q + 3]);
    }
}

// ---------------- 4,6,8: agg — 4 nodes/warp, fp16 gather, unrolled 8-trip loop --------
template <int L>
__global__ void __launch_bounds__(256) k_agg(const float* __restrict__ bbc,
                                             const float* __restrict__ Wl3,
                                             const int* __restrict__ batch, int n, float invE) {
    constexpr int P = (L == 1) ? 1 : 0;       // h buffer: L0->0, L1->1, L2->0
    const uint2* hc = g_hh[P];
    int t = threadIdx.x, lane = t & 31, w = t >> 5;
    int node = lane >> 3;      // 0..3
    int hl   = lane & 7;       // lane within node (also column group)
    int slot = (blockIdx.x * 8 + w) * 4 + node;
    bool valid = slot < n;
    int dc = g_perm[valid ? slot : (n - 1)];

    const float* asc = g_as[P];
    float adst_d = g_ad[P][dc];
    float asrc_d = asc[dc];
    const float* pu = &g_prm[320 + 5 * L];
    float aloop = (g_easum[0] * pu[0] + g_easum[1] * pu[1] + g_easum[2] * pu[2]) * invE + pu[3];

    int beg = g_rp[dc], end = g_rp[dc + 1];
    int itersW = __reduce_max_sync(0xffffffffu, (end - beg + 7) >> 3);

    float4 acc = make_float4(0.f, 0.f, 0.f, 0.f);
    float denom = 0.f;
    for (int it = 0; it < itersW; it++) {
        int base = beg + (it << 3);
        int idx = base + hl;
        int s = 0; float ex = 0.f;
        if (idx < end) {
            float4 r = g_pack[idx];
            s = __float_as_int(r.x);
            float ae = (L == 0) ? r.y : (L == 1) ? r.z : r.w;
            ex = __expf(lrelu(asc[s] + adst_d + ae));
        }
        denom += ex;
        // fixed 8-trip unrolled gather: out-of-range lanes carry ex=0; MLP=8
#pragma unroll
        for (int k = 0; k < 8; k++) {
            int sl = (node << 3) + k;
            float exk = __shfl_sync(0xffffffffu, ex, sl);
            int   sk  = __shfl_sync(0xffffffffu, s, sl);
            float4 hv = unp4h(hc[sk * 8 + hl]);
            acc.x += exk * hv.x; acc.y += exk * hv.y;
            acc.z += exk * hv.z; acc.w += exk * hv.w;
        }
    }
    denom += __shfl_xor_sync(0xffffffffu, denom, 1);
    denom += __shfl_xor_sync(0xffffffffu, denom, 2);
    denom += __shfl_xor_sync(0xffffffffu, denom, 4);

    float le = __expf(lrelu(asrc_d + adst_d + aloop));
    float inv = 1.f / (denom + le + 1e-16f);
    float4 hd4 = unp4h(hc[dc * 8 + hl]);
    float4 bb4 = ((const float4*)bbc)[hl];
    float4 wl4 = ((const float4*)Wl3)[L * 8 + hl];
    float4 y4;
    y4.x = (acc.x + le * hd4.x) * inv + bb4.x;
    y4.y = (acc.y + le * hd4.y) * inv + bb4.y;
    y4.z = (acc.z + le * hd4.z) * inv + bb4.z;
    y4.w = (acc.w + le * hd4.w) * inv + bb4.w;
    float v = y4.x * wl4.x + y4.y * wl4.y + y4.z * wl4.z + y4.w * wl4.w;
    v += __shfl_xor_sync(0xffffffffu, v, 1);
    v += __shfl_xor_sync(0xffffffffu, v, 2);
    v += __shfl_xor_sync(0xffffffffu, v, 4);
    if (valid) {
        if (L < 2) {
            g_y4[dc * 8 + hl] = y4;
            if (hl == 0) {
                if (L == 0) g_vacc[dc] = v;
                else        g_vacc[dc] += v;
            }
        } else if (hl == 0) {
            int gg = batch[dc];
            atomicAdd(&g_gsum[gg], g_vacc[dc] + v);
            atomicAdd(&g_gcnt[gg], 1.f);
        }
    }
}

// ---------------- 5,7: node transform h' = y @ W, attn scalars (thread per node) ------
__global__ void __launch_bounds__(256) k_nodeT(const float* __restrict__ W,
                                               const float* __restrict__ as_,
                                               const float* __restrict__ ad_,
                                               int hbuf, int abuf, int n) {
    __shared__ float Ws[1024], av[64];
    int t = threadIdx.x;
    for (int k = t; k < 1024; k += 256) Ws[k] = W[k];
    if (t < 32) { av[t] = as_[t]; av[32 + t] = ad_[t]; }
    __syncthreads();
    int i = blockIdx.x * 256 + t;
    if (i >= n) return;
    const float4* yv4 = &g_y4[i * 8];
    float acc[32];
#pragma unroll
    for (int j = 0; j < 32; j++) acc[j] = 0.f;
#pragma unroll
    for (int q = 0; q < 8; q++) {
        float4 yv = yv4[q];
#pragma unroll
        for (int j = 0; j < 32; j++)
            acc[j] += yv.x * Ws[(4 * q) * 32 + j]     + yv.y * Ws[(4 * q + 1) * 32 + j]
                    + yv.z * Ws[(4 * q + 2) * 32 + j] + yv.w * Ws[(4 * q + 3) * 32 + j];
    }
    float sa = 0.f, sd = 0.f;
#pragma unroll
    for (int j = 0; j < 32; j++) { sa += acc[j] * av[j]; sd += acc[j] * av[32 + j]; }
    g_as[abuf][i] = sa; g_ad[abuf][i] = sd;
    uint2* o = &g_hh[hbuf][i * 8];
#pragma unroll
    for (int q = 0; q < 8; q++)
        o[q] = pack4h(acc[4 * q], acc[4 * q + 1], acc[4 * q + 2], acc[4 * q + 3]);
}

// ---------------- 9: final mean + bias, restore zeros ----------------
__global__ void k_final(float* __restrict__ out, const float* __restrict__ b_l3, int G) {
    int g = blockIdx.x * blockDim.x + threadIdx.x;
    if (g == 0) { g_bc0 = 0; g_bc1 = 0; }
    if (g < 3) g_easum[g] = 0.f;
    if (g < G) {
        out[g] = g_gsum[g] / fmaxf(g_gcnt[g], 1.f) + b_l3[0];
        g_gsum[g] = 0.f;
        g_gcnt[g] = 0.f;
    }
}

// ---------------- launch ----------------
extern "C" void kernel_launch(void* const* d_in, const int* in_sizes, int n_in,
                              void* d_out, int out_size) {
    const float* nf    = (const float*)d_in[0];
    const int*   ei    = (const int*)d_in[1];
    const float* ea    = (const float*)d_in[2];
    const int*   batch = (const int*)d_in[3];
    const float* W_ne  = (const float*)d_in[4];
    const float* b_ne  = (const float*)d_in[5];
    const float* W_ee  = (const float*)d_in[6];
    const float* b_ee  = (const float*)d_in[7];
    const float* W_l3  = (const float*)d_in[8];
    const float* b_l3  = (const float*)d_in[9];
    const float* W[3]   = {(const float*)d_in[10], (const float*)d_in[16], (const float*)d_in[22]};
    const float* as_[3] = {(const float*)d_in[11], (const float*)d_in[17], (const float*)d_in[23]};
    const float* ad_[3] = {(const float*)d_in[12], (const float*)d_in[18], (const float*)d_in[24]};
    const float* We_[3] = {(const float*)d_in[13], (const float*)d_in[19], (const float*)d_in[25]};
    const float* ae_[3] = {(const float*)d_in[14], (const float*)d_in[20], (const float*)d_in[26]};
    const float* bb_[3] = {(const float*)d_in[15], (const float*)d_in[21], (const float*)d_in[27]};

    int n = in_sizes[3];
    int E = in_sizes[1] / 2;
    int G = out_size;
    const int* src = ei;
    const int* dst = ei + E;
    float invE = 1.f / (float)E;

    int eb  = (E + 255) / 256;
    int nb  = (n + 255) / 256;
    int nbw = (n + 31) / 32;
    int nch = (n + CHUNK - 1) / CHUNK;

    k_countB<<<eb, 256>>>(dst, E);
    k_scans<<<nch + 1, 256>>>(W_ne, b_ne, W_ee, b_ee, W[0],
                              We_[0], ae_[0], We_[1], ae_[1], We_[2], ae_[2], nch, n);
    k_build<<<eb + nb, 256>>>(src, dst, ea, nf, as_[0], ad_[0], E, n, eb);
    k_agg<0><<<nbw, 256>>>(bb_[0], W_l3, batch, n, invE);
    k_nodeT<<<nb, 256>>>(W[1], as_[1], ad_[1], 1, 1, n);
    k_agg<1><<<nbw, 256>>>(bb_[1], W_l3, batch, n, invE);
    k_nodeT<<<nb, 256>>>(W[2], as_[2], ad_[2], 0, 0, n);
    k_agg<2><<<nbw, 256>>>(bb_[2], W_l3, batch, n, invE);
    k_final<<<1, 128>>>((float*)d_out, b_l3, G);
}